// round 15
// baseline (speedup 1.0000x reference)
#include <cuda_runtime.h>
#include <math.h>
#include <stdint.h>

#define Bsz 128
#define Ssz 1024
#define Hsz 768
#define MAXV 25
#define NTOK 50                 // 2*MAXV
#define S_LEVI (Ssz - NTOK)     // 974
#define H4 (Hsz / 4)            // 192 float4 per row

// ---- GEMM config (R15: 4b x 8h microtile, 64b x 128h x 48k tiles,
//      KSPLIT=16, fused last-block reduction) ----
#define KSPLIT 16               // 768 / 16 = 48 k per block
#define KS   48                 // k per block
#define GTB  64                 // batches per block
#define GTH  128                // h-outputs per block
#define SPST 65                 // sP row stride (floats)
#define SWST 132                // sW row stride (floats), 16B multiple
#define NTILE ((Bsz / GTB) * (Hsz / GTH))   // 12 output tiles

// Scratch (allocation-free rule: device globals)
__device__ float g_pooled[Bsz * Hsz];
__device__ float g_part[KSPLIT * Bsz * Hsz];   // 6.3 MB partial sums
__device__ int   g_cnt[NTILE];                 // zero-init; reset by last block

__device__ __forceinline__ float warp_sum(float v) {
#pragma unroll
    for (int o = 16; o > 0; o >>= 1) v += __shfl_xor_sync(0xffffffffu, v, o);
    return v;
}

__device__ __forceinline__ uint32_t smem_u32(const void* p) {
    uint32_t a;
    asm("{ .reg .u64 t; cvta.to.shared.u64 t, %1; cvt.u32.u64 %0, t; }"
        : "=r"(a) : "l"(p));
    return a;
}

// pack (f,f) into a 64-bit f32x2 register
#define PACK_DUP(dst, f) \
    asm("mov.b64 %0, {%1, %1};" : "=l"(dst) : "r"(__float_as_uint(f)))

// d.lo += a.lo*b.lo; d.hi += a.hi*b.hi  (two fp32 FMAs, one FFMA2)
#define FMA2(d, a, b) \
    asm("fma.rn.f32x2 %0, %1, %2, %0;" : "+l"(d) : "l"(a), "l"(b))

// Detect verb_count dtype (int64 vs int32) and return v for batch b.
// 64 odd-word samples all zero <=> int64 (values < 25). Warp-collective.
__device__ __forceinline__ int load_verb(const int* __restrict__ verb32,
                                         int b, int lane) {
    int a = verb32[2 * lane + 1];
    int c = verb32[2 * lane + 65];
    unsigned nz = __ballot_sync(0xffffffffu, (a | c) != 0);
    return nz ? verb32[b] : verb32[2 * b];
}

// ---------------------------------------------------------------------------
// Kernel 1: fused masked-attention pooling. One block per batch, 768 threads.
// Active ordinals j in [0,2v): token t = j<v ? j : j-v+MAXV. Inactive rows
// have weight exactly 0 in the reference and are never touched. The
// subject-hidden score term is a per-batch constant over active tokens and
// cancels exactly in softmax; skipped.
// ---------------------------------------------------------------------------
__global__ __launch_bounds__(768, 1)
void pool_kernel(const float* __restrict__ hidden,
                 const int*   __restrict__ verb32,
                 const float* __restrict__ align_w,   // [2H]
                 float*       __restrict__ pooled)    // [B,H]
{
    __shared__ float  s_scores[NTOK];     // by active ordinal j
    __shared__ float  s_wact[NTOK];       // weight of ordinal j
    __shared__ float4 s_part[4][H4];      // 12 KB cross-group pooling partials

    const int b    = blockIdx.x;
    const int tid  = threadIdx.x;
    const int warp = tid >> 5;
    const int lane = tid & 31;

    const int v    = load_verb(verb32, b, lane);   // warp-uniform
    const int nact = 2 * v;

    if (tid < NTOK) s_scores[tid] = -INFINITY;
    __syncthreads();

    const float* __restrict__ bbase = hidden + ((size_t)b * Ssz + S_LEVI) * Hsz;
    const float4* __restrict__ base4 = (const float4*)bbase;
    const float4* __restrict__ w4    = (const float4*)(align_w + Hsz);

    // --- pass 1: scores, warp per active ordinal (24 warps, <=2 rounds) ---
    for (int j = warp; j < nact; j += 24) {
        const int t = (j < v) ? j : (j - v + MAXV);
        const float4* row4 = base4 + (size_t)t * H4;
        float4 a = make_float4(0.f, 0.f, 0.f, 0.f);
#pragma unroll
        for (int i = 0; i < 6; i++) {
            float4 hv = row4[lane + i * 32];
            float4 wv = w4[lane + i * 32];
            a.x = fmaf(hv.x, wv.x, a.x);
            a.y = fmaf(hv.y, wv.y, a.y);
            a.z = fmaf(hv.z, wv.z, a.z);
            a.w = fmaf(hv.w, wv.w, a.w);
        }
        float s = warp_sum((a.x + a.y) + (a.z + a.w));
        if (lane == 0) s_scores[j] = s;
    }
    __syncthreads();

    // --- pass 2: softmax over ordinals (warp 0) ---
    if (warp == 0) {
        float a  = (lane < NTOK)      ? s_scores[lane]      : -INFINITY;
        float b2 = (lane + 32 < NTOK) ? s_scores[lane + 32] : -INFINITY;
        float m = fmaxf(a, b2);
#pragma unroll
        for (int o = 16; o > 0; o >>= 1)
            m = fmaxf(m, __shfl_xor_sync(0xffffffffu, m, o));
        if (!isfinite(m)) m = 0.f;
        float e1 = (a  > -INFINITY) ? expf(a  - m) : 0.f;
        float e2 = (b2 > -INFINITY) ? expf(b2 - m) : 0.f;
        float denom = warp_sum(e1 + e2);
        float inv = (denom > 0.f) ? (1.f / fmaxf(denom, 1e-30f)) : 0.f;
        if (lane < NTOK)      s_wact[lane]      = e1 * inv;
        if (lane + 32 < NTOK) s_wact[lane + 32] = e2 * inv;
    }
    __syncthreads();

    // --- pass 3: pooled, (4 token-groups x 192 h-chunks) then smem reduce ---
    {
        const int grp = tid / H4;     // 0..3
        const int h4  = tid % H4;     // 0..191
        float4 acc = make_float4(0.f, 0.f, 0.f, 0.f);
#pragma unroll 2
        for (int j = grp; j < nact; j += 4) {
            const int t = (j < v) ? j : (j - v + MAXV);
            const float w = s_wact[j];
            float4 hv = base4[(size_t)t * H4 + h4];
            acc.x = fmaf(w, hv.x, acc.x);
            acc.y = fmaf(w, hv.y, acc.y);
            acc.z = fmaf(w, hv.z, acc.z);
            acc.w = fmaf(w, hv.w, acc.w);
        }
        s_part[grp][h4] = acc;
    }
    __syncthreads();

    if (tid < H4) {
        float4 p0 = s_part[0][tid], p1 = s_part[1][tid];
        float4 p2 = s_part[2][tid], p3 = s_part[3][tid];
        float4 r;
        r.x = (p0.x + p1.x) + (p2.x + p3.x);
        r.y = (p0.y + p1.y) + (p2.y + p3.y);
        r.z = (p0.z + p1.z) + (p2.z + p3.z);
        r.w = (p0.w + p1.w) + (p2.w + p3.w);
        ((float4*)pooled)[(size_t)b * H4 + tid] = r;
    }
}

// ---------------------------------------------------------------------------
// Kernel 2: split-K GEMM, one 64b x 128h x 48k tile per block, grid
// (6,2,16)=192 blocks, 256 threads. Per-thread 4b x 8h microtile via FFMA2;
// W pairs come packed straight from ld.shared.v2.u64, only the 4 P
// broadcasts need packing. 32 independent acc chains = high ILP at low occ.
// Fused deterministic last-block reduction + bias + tanh
// (threadFenceReduction pattern, counter self-reset for graph replay).
// ---------------------------------------------------------------------------
__global__ __launch_bounds__(256, 2)
void gemm_fused(const float* __restrict__ P,     // [B,H] pooled
                const float* __restrict__ W,     // [H,H] out_w (k contiguous)
                const float* __restrict__ bias,  // [H]
                float*       __restrict__ part,  // [KSPLIT,B,H] scratch
                float*       __restrict__ out)   // [B,H]
{
    __shared__ __align__(16) float sP[KS][SPST];   // k-major: 12.5 KB
    __shared__ __align__(16) float sW[KS][SWST];   // k-major: 25.3 KB
    __shared__ int s_last;

    const int tid  = threadIdx.x;
    const int h0   = blockIdx.x * GTH;
    const int b0   = blockIdx.y * GTB;
    const int ks0  = blockIdx.z * KS;
    const int tileId = blockIdx.y * gridDim.x + blockIdx.x;

    // --- load P tile 64 x 48 (12 float4/row -> 768 float4, 3/thread) ---
#pragma unroll
    for (int i = 0; i < 3; i++) {
        int idx = tid + i * 256;            // 0..767
        int row = idx / 12, c4 = idx % 12;
        float4 vv = *(const float4*)&P[(size_t)(b0 + row) * Hsz + ks0 + c4 * 4];
        sP[c4 * 4 + 0][row] = vv.x;
        sP[c4 * 4 + 1][row] = vv.y;
        sP[c4 * 4 + 2][row] = vv.z;
        sP[c4 * 4 + 3][row] = vv.w;
    }
    // --- load W tile 128 x 48 (12 float4/row -> 1536 float4, 6/thread) ---
#pragma unroll
    for (int i = 0; i < 6; i++) {
        int idx = tid + i * 256;            // 0..1535
        int hh = idx / 12, c4 = idx % 12;
        float4 vv = *(const float4*)&W[(size_t)(h0 + hh) * Hsz + ks0 + c4 * 4];
        sW[c4 * 4 + 0][hh] = vv.x;
        sW[c4 * 4 + 1][hh] = vv.y;
        sW[c4 * 4 + 2][hh] = vv.z;
        sW[c4 * 4 + 3][hh] = vv.w;
    }
    __syncthreads();

    // --- compute: b rows {rb, rb+16, rb+32, rb+48}, h cols c*8 .. c*8+7 ---
    const int warp = tid >> 5;
    const int lane = tid & 31;
    const int c    = lane & 15;                    // 0..15 -> 8 h each
    const int rb   = (warp << 1) | (lane >> 4);    // 0..15

    const uint32_t swa = smem_u32(&sW[0][c * 8]);

    unsigned long long acc[16];   // [b i][h-pair j]
#pragma unroll
    for (int i = 0; i < 16; i++) acc[i] = 0ull;

#pragma unroll 4
    for (int k = 0; k < KS; k++) {
        unsigned long long w01, w23, w45, w67;
        asm("ld.shared.v2.u64 {%0, %1}, [%2];"
            : "=l"(w01), "=l"(w23) : "r"(swa + k * (SWST * 4)));
        asm("ld.shared.v2.u64 {%0, %1}, [%2];"
            : "=l"(w45), "=l"(w67) : "r"(swa + k * (SWST * 4) + 16));
        float p0 = sP[k][rb];
        float p1 = sP[k][rb + 16];
        float p2 = sP[k][rb + 32];
        float p3 = sP[k][rb + 48];
        unsigned long long pp0, pp1, pp2, pp3;
        PACK_DUP(pp0, p0); PACK_DUP(pp1, p1);
        PACK_DUP(pp2, p2); PACK_DUP(pp3, p3);
        FMA2(acc[0],  pp0, w01); FMA2(acc[1],  pp0, w23);
        FMA2(acc[2],  pp0, w45); FMA2(acc[3],  pp0, w67);
        FMA2(acc[4],  pp1, w01); FMA2(acc[5],  pp1, w23);
        FMA2(acc[6],  pp1, w45); FMA2(acc[7],  pp1, w67);
        FMA2(acc[8],  pp2, w01); FMA2(acc[9],  pp2, w23);
        FMA2(acc[10], pp2, w45); FMA2(acc[11], pp2, w67);
        FMA2(acc[12], pp3, w01); FMA2(acc[13], pp3, w23);
        FMA2(acc[14], pp3, w45); FMA2(acc[15], pp3, w67);
    }

    // --- store partials: 4 rows x 2 float4 per thread ---
    {
        float* base = part + ((size_t)blockIdx.z * Bsz) * Hsz;
#pragma unroll
        for (int i = 0; i < 4; i++) {
            float* dst = &base[(size_t)(b0 + rb + 16 * i) * Hsz + h0 + c * 8];
            float4 s;
            asm("mov.b64 {%0, %1}, %2;" : "=f"(s.x), "=f"(s.y) : "l"(acc[i * 4 + 0]));
            asm("mov.b64 {%0, %1}, %2;" : "=f"(s.z), "=f"(s.w) : "l"(acc[i * 4 + 1]));
            *(float4*)dst = s;
            asm("mov.b64 {%0, %1}, %2;" : "=f"(s.x), "=f"(s.y) : "l"(acc[i * 4 + 2]));
            asm("mov.b64 {%0, %1}, %2;" : "=f"(s.z), "=f"(s.w) : "l"(acc[i * 4 + 3]));
            *(float4*)(dst + 4) = s;
        }
    }

    // --- last-block-reduces (threadFenceReduction pattern) ---
    __threadfence();
    if (tid == 0) {
        int old = atomicAdd(&g_cnt[tileId], 1);
        int last = (old == KSPLIT - 1);
        if (last) g_cnt[tileId] = 0;   // reset for next graph replay
        s_last = last;
    }
    __syncthreads();
    if (!s_last) return;

    // reduce this tile: same slots as compute; z in fixed order -> deterministic
#pragma unroll
    for (int i = 0; i < 4; i++) {
        const size_t off = (size_t)(b0 + rb + 16 * i) * Hsz + h0 + c * 8;
        float4 s0 = make_float4(0.f, 0.f, 0.f, 0.f);
        float4 s1 = make_float4(0.f, 0.f, 0.f, 0.f);
#pragma unroll
        for (int z = 0; z < KSPLIT; z++) {
            const float* src = &part[(size_t)z * Bsz * Hsz + off];
            float4 a = *(const float4*)src;
            float4 bq = *(const float4*)(src + 4);
            s0.x += a.x;  s0.y += a.y;  s0.z += a.z;  s0.w += a.w;
            s1.x += bq.x; s1.y += bq.y; s1.z += bq.z; s1.w += bq.w;
        }
        const float4 bi0 = *(const float4*)&bias[h0 + c * 8];
        const float4 bi1 = *(const float4*)&bias[h0 + c * 8 + 4];
        float4 o0, o1;
        o0.x = tanhf(s0.x + bi0.x); o0.y = tanhf(s0.y + bi0.y);
        o0.z = tanhf(s0.z + bi0.z); o0.w = tanhf(s0.w + bi0.w);
        o1.x = tanhf(s1.x + bi1.x); o1.y = tanhf(s1.y + bi1.y);
        o1.z = tanhf(s1.z + bi1.z); o1.w = tanhf(s1.w + bi1.w);
        *(float4*)&out[off]     = o0;
        *(float4*)&out[off + 4] = o1;
    }
}

// ---------------------------------------------------------------------------
extern "C" void kernel_launch(void* const* d_in, const int* in_sizes, int n_in,
                              void* d_out, int out_size)
{
    const float* hidden   = (const float*)d_in[0];
    const int*   verb32   = (const int*)  d_in[1];  // int32 view; dtype auto-detected
    const float* align_w  = (const float*)d_in[3];
    const float* out_w    = (const float*)d_in[5];
    const float* out_b    = (const float*)d_in[6];
    float* out = (float*)d_out;

    float* pooled = nullptr;
    float* part   = nullptr;
    cudaGetSymbolAddress((void**)&pooled, g_pooled);
    cudaGetSymbolAddress((void**)&part,   g_part);

    pool_kernel<<<Bsz, 768>>>(hidden, verb32, align_w, pooled);
    gemm_fused<<<dim3(Hsz / GTH, Bsz / GTB, KSPLIT), 256>>>(pooled, out_w,
                                                            out_b, part, out);
}

// round 16
// speedup vs baseline: 1.4459x; 1.4459x over previous
#include <cuda_runtime.h>
#include <math.h>
#include <stdint.h>

#define Bsz 128
#define Ssz 1024
#define Hsz 768
#define MAXV 25
#define NTOK 50                 // 2*MAXV
#define S_LEVI (Ssz - NTOK)     // 974
#define H4 (Hsz / 4)            // 192 float4 per row

// ---- GEMM split-K config (R12 engine; KSPLIT 8->12, padded sP) ----
#define KSPLIT 12               // 768 / 12 = 64 k per split
#define GTB 32                  // batches per block
#define GTH 64                  // h-outputs per block
#define GTK 32                  // k per smem tile
#define NITER 2                 // 64 / 32
#define WPAD 4                  // sW row pad
#define NTILE ((Bsz / GTB) * (Hsz / GTH))   // 48 output tiles

// Scratch (allocation-free rule: device globals)
__device__ float g_pooled[Bsz * Hsz];
__device__ float g_part[KSPLIT * Bsz * Hsz];   // 4.7 MB partial sums
__device__ int   g_cnt[NTILE];                 // zero-init; reset by last block

__device__ __forceinline__ float warp_sum(float v) {
#pragma unroll
    for (int o = 16; o > 0; o >>= 1) v += __shfl_xor_sync(0xffffffffu, v, o);
    return v;
}

// Detect verb_count dtype (int64 vs int32) and return v for batch b.
// 64 odd-word samples all zero <=> int64 (values < 25). Warp-collective.
__device__ __forceinline__ int load_verb(const int* __restrict__ verb32,
                                         int b, int lane) {
    int a = verb32[2 * lane + 1];
    int c = verb32[2 * lane + 65];
    unsigned nz = __ballot_sync(0xffffffffu, (a | c) != 0);
    return nz ? verb32[b] : verb32[2 * b];
}

// ---------------------------------------------------------------------------
// Kernel 1: register-resident masked-attention pooling. One block per batch,
// 512 threads (16 warps). Warp w owns ordinals {w, w+16, w+32}; it loads the
// corresponding active rows ONCE into registers (all loads issued up front,
// MLP ~18), computes scores, and after softmax scales the held rows by their
// weights. Cross-warp h-sum via smem partials. Inactive rows (weight exactly
// 0 in the reference) are never read. Subject-hidden score term is a
// per-batch constant over active tokens; cancels in softmax; skipped.
// ---------------------------------------------------------------------------
__global__ __launch_bounds__(512, 1)
void pool_kernel(const float* __restrict__ hidden,
                 const int*   __restrict__ verb32,
                 const float* __restrict__ align_w,   // [2H]
                 float*       __restrict__ pooled)    // [B,H]
{
    __shared__ float  s_scores[NTOK];     // by active ordinal j
    __shared__ float  s_wact[NTOK];       // weight of ordinal j
    __shared__ float4 s_part[16][H4];     // 48 KB per-warp pooling partials

    const int b    = blockIdx.x;
    const int tid  = threadIdx.x;
    const int warp = tid >> 5;            // 0..15
    const int lane = tid & 31;

    const int v    = load_verb(verb32, b, lane);   // warp-uniform
    const int nact = 2 * v;

    if (tid < NTOK) s_scores[tid] = -INFINITY;
    __syncthreads();   // init visible before pass-1 writes

    const float4* __restrict__ base4 =
        (const float4*)(hidden + ((size_t)b * Ssz + S_LEVI) * Hsz);
    const float4* __restrict__ w4 = (const float4*)(align_w + Hsz);

    // ordinals owned by this warp
    const int j0 = warp, j1 = warp + 16, j2 = warp + 32;
    const bool a0 = j0 < nact, a1 = j1 < nact, a2 = j2 < nact;
    const int t0 = (j0 < v) ? j0 : (j0 - v + MAXV);
    const int t1 = (j1 < v) ? j1 : (j1 - v + MAXV);
    const int t2 = (j2 < v) ? j2 : (j2 - v + MAXV);

    float4 r0[6], r1[6], r2[6];
    // issue ALL row loads first (up to 18 independent float4 loads in flight)
    if (a0) {
        const float4* p = base4 + (size_t)t0 * H4;
#pragma unroll
        for (int i = 0; i < 6; i++) r0[i] = p[lane + i * 32];
    }
    if (a1) {
        const float4* p = base4 + (size_t)t1 * H4;
#pragma unroll
        for (int i = 0; i < 6; i++) r1[i] = p[lane + i * 32];
    }
    if (a2) {
        const float4* p = base4 + (size_t)t2 * H4;
#pragma unroll
        for (int i = 0; i < 6; i++) r2[i] = p[lane + i * 32];
    }

    // dots vs align_w[H:2H] (w2 loads L1-hot across warps)
    {
        float d0 = 0.f, d1 = 0.f, d2 = 0.f;
#pragma unroll
        for (int i = 0; i < 6; i++) {
            float4 wv = w4[lane + i * 32];
            if (a0) { d0 = fmaf(r0[i].x, wv.x, d0); d0 = fmaf(r0[i].y, wv.y, d0);
                      d0 = fmaf(r0[i].z, wv.z, d0); d0 = fmaf(r0[i].w, wv.w, d0); }
            if (a1) { d1 = fmaf(r1[i].x, wv.x, d1); d1 = fmaf(r1[i].y, wv.y, d1);
                      d1 = fmaf(r1[i].z, wv.z, d1); d1 = fmaf(r1[i].w, wv.w, d1); }
            if (a2) { d2 = fmaf(r2[i].x, wv.x, d2); d2 = fmaf(r2[i].y, wv.y, d2);
                      d2 = fmaf(r2[i].z, wv.z, d2); d2 = fmaf(r2[i].w, wv.w, d2); }
        }
        d0 = warp_sum(d0); d1 = warp_sum(d1); d2 = warp_sum(d2);
        if (lane == 0) {
            if (a0) s_scores[j0] = d0;
            if (a1) s_scores[j1] = d1;
            if (a2) s_scores[j2] = d2;
        }
    }
    __syncthreads();

    // softmax over ordinals (warp 0)
    if (warp == 0) {
        float a  = (lane < NTOK)      ? s_scores[lane]      : -INFINITY;
        float b2 = (lane + 32 < NTOK) ? s_scores[lane + 32] : -INFINITY;
        float m = fmaxf(a, b2);
#pragma unroll
        for (int o = 16; o > 0; o >>= 1)
            m = fmaxf(m, __shfl_xor_sync(0xffffffffu, m, o));
        if (!isfinite(m)) m = 0.f;
        float e1 = (a  > -INFINITY) ? expf(a  - m) : 0.f;
        float e2 = (b2 > -INFINITY) ? expf(b2 - m) : 0.f;
        float denom = warp_sum(e1 + e2);
        float inv = (denom > 0.f) ? (1.f / fmaxf(denom, 1e-30f)) : 0.f;
        if (lane < NTOK)      s_wact[lane]      = e1 * inv;
        if (lane + 32 < NTOK) s_wact[lane + 32] = e2 * inv;
    }
    __syncthreads();

    // weighted sum of HELD rows -> per-warp partial
    {
        const float w0 = a0 ? s_wact[j0] : 0.f;
        const float w1 = a1 ? s_wact[j1] : 0.f;
        const float w2s = a2 ? s_wact[j2] : 0.f;
#pragma unroll
        for (int i = 0; i < 6; i++) {
            float4 acc = make_float4(0.f, 0.f, 0.f, 0.f);
            if (a0) { acc.x = fmaf(w0, r0[i].x, acc.x); acc.y = fmaf(w0, r0[i].y, acc.y);
                      acc.z = fmaf(w0, r0[i].z, acc.z); acc.w = fmaf(w0, r0[i].w, acc.w); }
            if (a1) { acc.x = fmaf(w1, r1[i].x, acc.x); acc.y = fmaf(w1, r1[i].y, acc.y);
                      acc.z = fmaf(w1, r1[i].z, acc.z); acc.w = fmaf(w1, r1[i].w, acc.w); }
            if (a2) { acc.x = fmaf(w2s, r2[i].x, acc.x); acc.y = fmaf(w2s, r2[i].y, acc.y);
                      acc.z = fmaf(w2s, r2[i].z, acc.z); acc.w = fmaf(w2s, r2[i].w, acc.w); }
            s_part[warp][lane + i * 32] = acc;
        }
    }
    __syncthreads();

    // final reduce over 16 warps (192 threads, one float4 column each)
    if (tid < H4) {
        float4 s = make_float4(0.f, 0.f, 0.f, 0.f);
#pragma unroll
        for (int r = 0; r < 16; r++) {
            float4 p = s_part[r][tid];
            s.x += p.x; s.y += p.y; s.z += p.z; s.w += p.w;
        }
        ((float4*)pooled)[(size_t)b * H4 + tid] = s;
    }
}

// ---------------------------------------------------------------------------
// Kernel 2: split-K GEMM (R12 engine, unchanged microtile). 32b x 64h tiles,
// grid (12,4,12)=576 blocks, 256 threads, 2b x 4h per-thread microtile,
// double-buffered smem with register prefetch. sP padded (bank-conflict-free
// P broadcasts). Fused deterministic last-block reduction + bias + tanh
// (threadFenceReduction pattern, counter self-reset for graph replay).
// ---------------------------------------------------------------------------
__global__ __launch_bounds__(256, 3)
void gemm_fused(const float* __restrict__ P,     // [B,H] pooled
                const float* __restrict__ W,     // [H,H] out_w (k contiguous)
                const float* __restrict__ bias,  // [H]
                float*       __restrict__ part,  // [KSPLIT,B,H] scratch
                float*       __restrict__ out)   // [B,H]
{
    __shared__ float sP[2][GTB][GTK + 1];      // padded: conflict-free bcast
    __shared__ float sW[2][GTK][GTH + WPAD];   // 17.4 KB (k-major, padded)
    __shared__ int   s_last;

    const int tid  = threadIdx.x;
    const int h0   = blockIdx.x * GTH;
    const int b0   = blockIdx.y * GTB;
    const int ks0  = blockIdx.z * (Hsz / KSPLIT);
    const int tileId = blockIdx.y * gridDim.x + blockIdx.x;

    // compute mapping: 2 rows {r, r+16}, 4 cols at c4*4
    const int r  = tid >> 4;            // 0..15
    const int c4 = tid & 15;            // 0..15

    // tile-load mapping
    const int pr  = tid >> 3;           // 0..31  P row
    const int pc4 = tid & 7;            // 0..7   P float4 col

    float4 pre_p;
    float4 pre_w[2];

    // prefetch tile 0
    {
        const int kk = ks0;
        pre_p = *(const float4*)&P[(size_t)(b0 + pr) * Hsz + kk + pc4 * 4];
#pragma unroll
        for (int i = 0; i < 2; i++) {
            int q  = tid + i * 256;
            int hh = q >> 3, cc = q & 7;
            pre_w[i] = *(const float4*)&W[(size_t)(h0 + hh) * Hsz + kk + cc * 4];
        }
    }
    {
        sP[0][pr][pc4 * 4 + 0] = pre_p.x;
        sP[0][pr][pc4 * 4 + 1] = pre_p.y;
        sP[0][pr][pc4 * 4 + 2] = pre_p.z;
        sP[0][pr][pc4 * 4 + 3] = pre_p.w;
#pragma unroll
        for (int i = 0; i < 2; i++) {
            int q  = tid + i * 256;
            int hh = q >> 3, cc = q & 7;
            sW[0][cc * 4 + 0][hh] = pre_w[i].x;
            sW[0][cc * 4 + 1][hh] = pre_w[i].y;
            sW[0][cc * 4 + 2][hh] = pre_w[i].z;
            sW[0][cc * 4 + 3][hh] = pre_w[i].w;
        }
    }
    __syncthreads();

    float4 acc0 = make_float4(0.f, 0.f, 0.f, 0.f);
    float4 acc1 = make_float4(0.f, 0.f, 0.f, 0.f);

#pragma unroll
    for (int it = 0; it < NITER; it++) {
        const int cur = it & 1;

        if (it < NITER - 1) {
            const int kk = ks0 + (it + 1) * GTK;
            pre_p = *(const float4*)&P[(size_t)(b0 + pr) * Hsz + kk + pc4 * 4];
#pragma unroll
            for (int i = 0; i < 2; i++) {
                int q  = tid + i * 256;
                int hh = q >> 3, cc = q & 7;
                pre_w[i] = *(const float4*)&W[(size_t)(h0 + hh) * Hsz + kk + cc * 4];
            }
        }

#pragma unroll
        for (int k = 0; k < GTK; k++) {
            float4 wv = *(const float4*)&sW[cur][k][c4 * 4];
            float p0 = sP[cur][r][k];
            float p1 = sP[cur][r + 16][k];
            acc0.x = fmaf(p0, wv.x, acc0.x); acc0.y = fmaf(p0, wv.y, acc0.y);
            acc0.z = fmaf(p0, wv.z, acc0.z); acc0.w = fmaf(p0, wv.w, acc0.w);
            acc1.x = fmaf(p1, wv.x, acc1.x); acc1.y = fmaf(p1, wv.y, acc1.y);
            acc1.z = fmaf(p1, wv.z, acc1.z); acc1.w = fmaf(p1, wv.w, acc1.w);
        }

        if (it < NITER - 1) {
            __syncthreads();
            const int nxt = cur ^ 1;
            sP[nxt][pr][pc4 * 4 + 0] = pre_p.x;
            sP[nxt][pr][pc4 * 4 + 1] = pre_p.y;
            sP[nxt][pr][pc4 * 4 + 2] = pre_p.z;
            sP[nxt][pr][pc4 * 4 + 3] = pre_p.w;
#pragma unroll
            for (int i = 0; i < 2; i++) {
                int q  = tid + i * 256;
                int hh = q >> 3, cc = q & 7;
                sW[nxt][cc * 4 + 0][hh] = pre_w[i].x;
                sW[nxt][cc * 4 + 1][hh] = pre_w[i].y;
                sW[nxt][cc * 4 + 2][hh] = pre_w[i].z;
                sW[nxt][cc * 4 + 3][hh] = pre_w[i].w;
            }
            __syncthreads();
        }
    }

    // store this split's partials
    {
        float* base = part + ((size_t)blockIdx.z * Bsz) * Hsz;
        *(float4*)&base[(size_t)(b0 + r)      * Hsz + h0 + c4 * 4] = acc0;
        *(float4*)&base[(size_t)(b0 + r + 16) * Hsz + h0 + c4 * 4] = acc1;
    }

    // --- last-block-reduces (threadFenceReduction pattern) ---
    __threadfence();
    if (tid == 0) {
        int old = atomicAdd(&g_cnt[tileId], 1);
        int last = (old == KSPLIT - 1);
        if (last) g_cnt[tileId] = 0;   // reset for next graph replay
        s_last = last;
    }
    __syncthreads();
    if (!s_last) return;

    // reduce this tile: each thread its 2 (b,h4) slots, z in fixed order
    const int hb = h0 + c4 * 4;
    const float4 bi = *(const float4*)&bias[hb];
#pragma unroll
    for (int j = 0; j < 2; j++) {
        const size_t off = (size_t)(b0 + r + j * 16) * Hsz + hb;
        float4 s = make_float4(0.f, 0.f, 0.f, 0.f);
#pragma unroll
        for (int z = 0; z < KSPLIT; z++) {
            float4 pv = *(const float4*)&part[(size_t)z * Bsz * Hsz + off];
            s.x += pv.x; s.y += pv.y; s.z += pv.z; s.w += pv.w;
        }
        float4 o;
        o.x = tanhf(s.x + bi.x);
        o.y = tanhf(s.y + bi.y);
        o.z = tanhf(s.z + bi.z);
        o.w = tanhf(s.w + bi.w);
        *(float4*)&out[off] = o;
    }
}

// ---------------------------------------------------------------------------
extern "C" void kernel_launch(void* const* d_in, const int* in_sizes, int n_in,
                              void* d_out, int out_size)
{
    const float* hidden   = (const float*)d_in[0];
    const int*   verb32   = (const int*)  d_in[1];  // int32 view; dtype auto-detected
    const float* align_w  = (const float*)d_in[3];
    const float* out_w    = (const float*)d_in[5];
    const float* out_b    = (const float*)d_in[6];
    float* out = (float*)d_out;

    float* pooled = nullptr;
    float* part   = nullptr;
    cudaGetSymbolAddress((void**)&pooled, g_pooled);
    cudaGetSymbolAddress((void**)&part,   g_part);

    pool_kernel<<<Bsz, 512>>>(hidden, verb32, align_w, pooled);
    gemm_fused<<<dim3(Hsz / GTH, Bsz / GTB, KSPLIT), 256>>>(pooled, out_w,
                                                            out_b, part, out);
}

// round 17
// speedup vs baseline: 1.5911x; 1.1004x over previous
#include <cuda_runtime.h>
#include <math.h>
#include <stdint.h>

#define Bsz 128
#define Ssz 1024
#define Hsz 768
#define MAXV 25
#define NTOK 50                 // 2*MAXV
#define S_LEVI (Ssz - NTOK)     // 974
#define H4 (Hsz / 4)            // 192 float4 per row

// ---- tensor-core GEMM config ----
#define KSPLIT 8                // 768/8 = 96 k per block
#define KS     96
#define GTB    64               // batches per block (m)
#define GTH    64               // h per block (n)
#define TSTR   100              // smem row stride in floats (16B-mult, conflict-free)
#define NTILE  ((Bsz / GTB) * (Hsz / GTH))   // 24 output tiles
#define SM_A   (GTB * TSTR)                   // 6400 floats per A array
#define SM_B   (GTH * TSTR)
#define SMEM_BYTES ((2 * SM_A + 2 * SM_B) * 4)   // 102400 B

// Scratch (allocation-free rule: device globals)
__device__ float g_pooled[Bsz * Hsz];
__device__ float g_part[KSPLIT * Bsz * Hsz];   // 3.1 MB partial sums
__device__ int   g_cnt[NTILE];                 // zero-init; reset by last block

__device__ __forceinline__ float warp_sum(float v) {
#pragma unroll
    for (int o = 16; o > 0; o >>= 1) v += __shfl_xor_sync(0xffffffffu, v, o);
    return v;
}

__device__ __forceinline__ uint32_t smem_u32(const void* p) {
    uint32_t a;
    asm("{ .reg .u64 t; cvta.to.shared.u64 t, %1; cvt.u32.u64 %0, t; }"
        : "=r"(a) : "l"(p));
    return a;
}

#define LDSM_X4(r0, r1, r2, r3, addr) \
    asm volatile("ldmatrix.sync.aligned.m8n8.x4.shared.b16 {%0,%1,%2,%3}, [%4];" \
        : "=r"(r0), "=r"(r1), "=r"(r2), "=r"(r3) : "r"(addr))

#define MMA_TF32(d, a0, a1, a2, a3, b0, b1) \
    asm volatile("mma.sync.aligned.m16n8k8.row.col.f32.tf32.tf32.f32 " \
        "{%0,%1,%2,%3}, {%4,%5,%6,%7}, {%8,%9}, {%0,%1,%2,%3};" \
        : "+f"(d[0]), "+f"(d[1]), "+f"(d[2]), "+f"(d[3]) \
        : "r"(a0), "r"(a1), "r"(a2), "r"(a3), "r"(b0), "r"(b1))

// Detect verb_count dtype (int64 vs int32) and return v for batch b.
// 64 odd-word samples all zero <=> int64 (values < 25). Warp-collective.
__device__ __forceinline__ int load_verb(const int* __restrict__ verb32,
                                         int b, int lane) {
    int a = verb32[2 * lane + 1];
    int c = verb32[2 * lane + 65];
    unsigned nz = __ballot_sync(0xffffffffu, (a | c) != 0);
    return nz ? verb32[b] : verb32[2 * b];
}

// ---------------------------------------------------------------------------
// Kernel 1: register-resident masked-attention pooling (unchanged from R16).
// ---------------------------------------------------------------------------
__global__ __launch_bounds__(512, 1)
void pool_kernel(const float* __restrict__ hidden,
                 const int*   __restrict__ verb32,
                 const float* __restrict__ align_w,   // [2H]
                 float*       __restrict__ pooled)    // [B,H]
{
    __shared__ float  s_scores[NTOK];
    __shared__ float  s_wact[NTOK];
    __shared__ float4 s_part[16][H4];     // 48 KB per-warp pooling partials

    const int b    = blockIdx.x;
    const int tid  = threadIdx.x;
    const int warp = tid >> 5;
    const int lane = tid & 31;

    const int v    = load_verb(verb32, b, lane);
    const int nact = 2 * v;

    if (tid < NTOK) s_scores[tid] = -INFINITY;
    __syncthreads();

    const float4* __restrict__ base4 =
        (const float4*)(hidden + ((size_t)b * Ssz + S_LEVI) * Hsz);
    const float4* __restrict__ w4 = (const float4*)(align_w + Hsz);

    const int j0 = warp, j1 = warp + 16, j2 = warp + 32;
    const bool a0 = j0 < nact, a1 = j1 < nact, a2 = j2 < nact;
    const int t0 = (j0 < v) ? j0 : (j0 - v + MAXV);
    const int t1 = (j1 < v) ? j1 : (j1 - v + MAXV);
    const int t2 = (j2 < v) ? j2 : (j2 - v + MAXV);

    float4 r0[6], r1[6], r2[6];
    if (a0) {
        const float4* p = base4 + (size_t)t0 * H4;
#pragma unroll
        for (int i = 0; i < 6; i++) r0[i] = p[lane + i * 32];
    }
    if (a1) {
        const float4* p = base4 + (size_t)t1 * H4;
#pragma unroll
        for (int i = 0; i < 6; i++) r1[i] = p[lane + i * 32];
    }
    if (a2) {
        const float4* p = base4 + (size_t)t2 * H4;
#pragma unroll
        for (int i = 0; i < 6; i++) r2[i] = p[lane + i * 32];
    }

    {
        float d0 = 0.f, d1 = 0.f, d2 = 0.f;
#pragma unroll
        for (int i = 0; i < 6; i++) {
            float4 wv = w4[lane + i * 32];
            if (a0) { d0 = fmaf(r0[i].x, wv.x, d0); d0 = fmaf(r0[i].y, wv.y, d0);
                      d0 = fmaf(r0[i].z, wv.z, d0); d0 = fmaf(r0[i].w, wv.w, d0); }
            if (a1) { d1 = fmaf(r1[i].x, wv.x, d1); d1 = fmaf(r1[i].y, wv.y, d1);
                      d1 = fmaf(r1[i].z, wv.z, d1); d1 = fmaf(r1[i].w, wv.w, d1); }
            if (a2) { d2 = fmaf(r2[i].x, wv.x, d2); d2 = fmaf(r2[i].y, wv.y, d2);
                      d2 = fmaf(r2[i].z, wv.z, d2); d2 = fmaf(r2[i].w, wv.w, d2); }
        }
        d0 = warp_sum(d0); d1 = warp_sum(d1); d2 = warp_sum(d2);
        if (lane == 0) {
            if (a0) s_scores[j0] = d0;
            if (a1) s_scores[j1] = d1;
            if (a2) s_scores[j2] = d2;
        }
    }
    __syncthreads();

    if (warp == 0) {
        float a  = (lane < NTOK)      ? s_scores[lane]      : -INFINITY;
        float b2 = (lane + 32 < NTOK) ? s_scores[lane + 32] : -INFINITY;
        float m = fmaxf(a, b2);
#pragma unroll
        for (int o = 16; o > 0; o >>= 1)
            m = fmaxf(m, __shfl_xor_sync(0xffffffffu, m, o));
        if (!isfinite(m)) m = 0.f;
        float e1 = (a  > -INFINITY) ? expf(a  - m) : 0.f;
        float e2 = (b2 > -INFINITY) ? expf(b2 - m) : 0.f;
        float denom = warp_sum(e1 + e2);
        float inv = (denom > 0.f) ? (1.f / fmaxf(denom, 1e-30f)) : 0.f;
        if (lane < NTOK)      s_wact[lane]      = e1 * inv;
        if (lane + 32 < NTOK) s_wact[lane + 32] = e2 * inv;
    }
    __syncthreads();

    {
        const float w0 = a0 ? s_wact[j0] : 0.f;
        const float w1 = a1 ? s_wact[j1] : 0.f;
        const float w2s = a2 ? s_wact[j2] : 0.f;
#pragma unroll
        for (int i = 0; i < 6; i++) {
            float4 acc = make_float4(0.f, 0.f, 0.f, 0.f);
            if (a0) { acc.x = fmaf(w0, r0[i].x, acc.x); acc.y = fmaf(w0, r0[i].y, acc.y);
                      acc.z = fmaf(w0, r0[i].z, acc.z); acc.w = fmaf(w0, r0[i].w, acc.w); }
            if (a1) { acc.x = fmaf(w1, r1[i].x, acc.x); acc.y = fmaf(w1, r1[i].y, acc.y);
                      acc.z = fmaf(w1, r1[i].z, acc.z); acc.w = fmaf(w1, r1[i].w, acc.w); }
            if (a2) { acc.x = fmaf(w2s, r2[i].x, acc.x); acc.y = fmaf(w2s, r2[i].y, acc.y);
                      acc.z = fmaf(w2s, r2[i].z, acc.z); acc.w = fmaf(w2s, r2[i].w, acc.w); }
            s_part[warp][lane + i * 32] = acc;
        }
    }
    __syncthreads();

    if (tid < H4) {
        float4 s = make_float4(0.f, 0.f, 0.f, 0.f);
#pragma unroll
        for (int r = 0; r < 16; r++) {
            float4 p = s_part[r][tid];
            s.x += p.x; s.y += p.y; s.z += p.z; s.w += p.w;
        }
        ((float4*)pooled)[(size_t)b * H4 + tid] = s;
    }
}

// ---------------------------------------------------------------------------
// Kernel 2: tensor-core split-K GEMM (3xTF32 via mma.sync.m16n8k8).
// Block = 64b x 64h x 96k, grid (12,2,8)=192 blocks, 256 threads (8 warps,
// 4m x 2n; warp tile 16b x 32h). A = pooled (hi/lo), B = out_w rows (hi/lo);
// acc += Ahi*Bhi + Ahi*Blo + Alo*Bhi  (error ~2^-22, fp32 accumulate).
// Deterministic last-block reduction + bias + tanh (counter self-reset).
// ---------------------------------------------------------------------------
__global__ __launch_bounds__(256, 1)
void gemm_tc(const float* __restrict__ P,     // [B,H] pooled
             const float* __restrict__ W,     // [H,H] out_w (k contiguous)
             const float* __restrict__ bias,  // [H]
             float*       __restrict__ part,  // [KSPLIT,B,H] scratch
             float*       __restrict__ out)   // [B,H]
{
    extern __shared__ float smem_dyn[];
    float* sAhi = smem_dyn;                 // [GTB][TSTR]
    float* sAlo = smem_dyn + SM_A;
    float* sBhi = smem_dyn + 2 * SM_A;      // [GTH][TSTR]
    float* sBlo = smem_dyn + 2 * SM_A + SM_B;
    __shared__ int s_last;

    const int tid  = threadIdx.x;
    const int lane = tid & 31;
    const int warp = tid >> 5;
    const int h0   = blockIdx.x * GTH;
    const int b0   = blockIdx.y * GTB;
    const int ks0  = blockIdx.z * KS;
    const int tileId = blockIdx.y * gridDim.x + blockIdx.x;

    // --- load + split A (P tile 64x96) and B (W tile 64x96): hi/lo ---
    // 1536 float4 each; 6 per thread per tensor.
#pragma unroll
    for (int i = 0; i < 6; i++) {
        int idx = tid + i * 256;            // 0..1535
        int row = idx / 24, c4 = idx % 24;
        float4 va = *(const float4*)&P[(size_t)(b0 + row) * Hsz + ks0 + c4 * 4];
        float4 vb = *(const float4*)&W[(size_t)(h0 + row) * Hsz + ks0 + c4 * 4];
        int off = row * TSTR + c4 * 4;
        float4 hi, lo;
        uint32_t u;
        asm("cvt.rna.tf32.f32 %0, %1;" : "=r"(u) : "f"(va.x)); hi.x = __uint_as_float(u);
        asm("cvt.rna.tf32.f32 %0, %1;" : "=r"(u) : "f"(va.y)); hi.y = __uint_as_float(u);
        asm("cvt.rna.tf32.f32 %0, %1;" : "=r"(u) : "f"(va.z)); hi.z = __uint_as_float(u);
        asm("cvt.rna.tf32.f32 %0, %1;" : "=r"(u) : "f"(va.w)); hi.w = __uint_as_float(u);
        lo.x = va.x - hi.x; lo.y = va.y - hi.y; lo.z = va.z - hi.z; lo.w = va.w - hi.w;
        *(float4*)&sAhi[off] = hi;
        *(float4*)&sAlo[off] = lo;
        asm("cvt.rna.tf32.f32 %0, %1;" : "=r"(u) : "f"(vb.x)); hi.x = __uint_as_float(u);
        asm("cvt.rna.tf32.f32 %0, %1;" : "=r"(u) : "f"(vb.y)); hi.y = __uint_as_float(u);
        asm("cvt.rna.tf32.f32 %0, %1;" : "=r"(u) : "f"(vb.z)); hi.z = __uint_as_float(u);
        asm("cvt.rna.tf32.f32 %0, %1;" : "=r"(u) : "f"(vb.w)); hi.w = __uint_as_float(u);
        lo.x = vb.x - hi.x; lo.y = vb.y - hi.y; lo.z = vb.z - hi.z; lo.w = vb.w - hi.w;
        *(float4*)&sBhi[off] = hi;
        *(float4*)&sBlo[off] = lo;
    }
    __syncthreads();

    // --- warp tiling: 4m x 2n; warp tile 16 x 32 ---
    const int m0 = (warp & 3) * 16;
    const int nb = (warp >> 2) * 32;

    // ldmatrix row/col mapping (derived; see analysis)
    const int arow = m0 + (lane & 15);
    const int acol = (lane >> 4) << 2;
    const int brow = (lane & 7) + ((lane >> 4) << 3);
    const int bcol = ((lane >> 3) & 1) << 2;

    const uint32_t base = smem_u32(smem_dyn);
    uint32_t aAhi = base + (arow * TSTR + acol) * 4;
    uint32_t aAlo = aAhi + SM_A * 4;
    uint32_t aB0hi = base + (2 * SM_A + (nb + brow) * TSTR + bcol) * 4;
    uint32_t aB1hi = aB0hi + 16 * TSTR * 4;
    uint32_t aB0lo = aB0hi + SM_B * 4;
    uint32_t aB1lo = aB1hi + SM_B * 4;

    float acc[4][4];
#pragma unroll
    for (int j = 0; j < 4; j++)
#pragma unroll
        for (int q = 0; q < 4; q++) acc[j][q] = 0.f;

#pragma unroll
    for (int ks = 0; ks < KS / 8; ks++) {
        uint32_t ah0, ah1, ah2, ah3, al0, al1, al2, al3;
        uint32_t bh[8], bl[8];
        LDSM_X4(ah0, ah1, ah2, ah3, aAhi);
        LDSM_X4(al0, al1, al2, al3, aAlo);
        LDSM_X4(bh[0], bh[1], bh[2], bh[3], aB0hi);
        LDSM_X4(bh[4], bh[5], bh[6], bh[7], aB1hi);
        LDSM_X4(bl[0], bl[1], bl[2], bl[3], aB0lo);
        LDSM_X4(bl[4], bl[5], bl[6], bl[7], aB1lo);
        aAhi += 32; aAlo += 32;
        aB0hi += 32; aB1hi += 32; aB0lo += 32; aB1lo += 32;

#pragma unroll
        for (int j = 0; j < 4; j++) {
            MMA_TF32(acc[j], ah0, ah1, ah2, ah3, bh[2 * j], bh[2 * j + 1]);
            MMA_TF32(acc[j], ah0, ah1, ah2, ah3, bl[2 * j], bl[2 * j + 1]);
            MMA_TF32(acc[j], al0, al1, al2, al3, bh[2 * j], bh[2 * j + 1]);
        }
    }

    // --- store partials: C thread layout of m16n8 ---
    {
        float* basep = part + ((size_t)blockIdx.z * Bsz) * Hsz;
        const int crow = b0 + m0 + (lane >> 2);
        const int ccol = h0 + nb + 2 * (lane & 3);
#pragma unroll
        for (int j = 0; j < 4; j++) {
            *(float2*)&basep[(size_t)crow * Hsz + ccol + 8 * j] =
                make_float2(acc[j][0], acc[j][1]);
            *(float2*)&basep[(size_t)(crow + 8) * Hsz + ccol + 8 * j] =
                make_float2(acc[j][2], acc[j][3]);
        }
    }

    // --- last-block-reduces (threadFenceReduction pattern) ---
    __threadfence();
    if (tid == 0) {
        int old = atomicAdd(&g_cnt[tileId], 1);
        int last = (old == KSPLIT - 1);
        if (last) g_cnt[tileId] = 0;   // reset for next graph replay
        s_last = last;
    }
    __syncthreads();
    if (!s_last) return;

    // reduce this 64x64 tile: 1024 float4 slots, 4 per thread; z fixed order
#pragma unroll
    for (int q = 0; q < 4; q++) {
        int pos = tid + q * 256;            // 0..1023
        int row = pos >> 4, c4 = pos & 15;
        const size_t off = (size_t)(b0 + row) * Hsz + h0 + c4 * 4;
        float4 s = make_float4(0.f, 0.f, 0.f, 0.f);
#pragma unroll
        for (int z = 0; z < KSPLIT; z++) {
            float4 pv = *(const float4*)&part[(size_t)z * Bsz * Hsz + off];
            s.x += pv.x; s.y += pv.y; s.z += pv.z; s.w += pv.w;
        }
        float4 bi = *(const float4*)&bias[h0 + c4 * 4];
        float4 o;
        o.x = tanhf(s.x + bi.x);
        o.y = tanhf(s.y + bi.y);
        o.z = tanhf(s.z + bi.z);
        o.w = tanhf(s.w + bi.w);
        *(float4*)&out[off] = o;
    }
}

// ---------------------------------------------------------------------------
extern "C" void kernel_launch(void* const* d_in, const int* in_sizes, int n_in,
                              void* d_out, int out_size)
{
    const float* hidden   = (const float*)d_in[0];
    const int*   verb32   = (const int*)  d_in[1];  // int32 view; dtype auto-detected
    const float* align_w  = (const float*)d_in[3];
    const float* out_w    = (const float*)d_in[5];
    const float* out_b    = (const float*)d_in[6];
    float* out = (float*)d_out;

    float* pooled = nullptr;
    float* part   = nullptr;
    cudaGetSymbolAddress((void**)&pooled, g_pooled);
    cudaGetSymbolAddress((void**)&part,   g_part);

    cudaFuncSetAttribute(gemm_tc,
                         cudaFuncAttributeMaxDynamicSharedMemorySize, SMEM_BYTES);

    pool_kernel<<<Bsz, 512>>>(hidden, verb32, align_w, pooled);
    gemm_tc<<<dim3(Hsz / GTH, Bsz / GTB, KSPLIT), 256, SMEM_BYTES>>>(
        pooled, out_w, out_b, part, out);
}